// round 2
// baseline (speedup 1.0000x reference)
#include <cuda_runtime.h>
#include <math.h>

#define B_  256
#define G_  4000
#define P_  128
#define H_  64
#define O_  16
#define GH_ 128
#define CH_ 8
#define C_  5
#define D_  12000
#define KSPLIT 16
#define KC 250        // G_/KSPLIT
#define TG 128        // gene tile in expert kernel
#define EPS_ 1e-5f

// ---------------- scratch (__device__ globals; no allocs) ----------------
__device__ float g_part[KSPLIT * B_ * GH_];   // gate hidden partials [ks][b][h]
__device__ int   g_glist[P_ * G_];            // active gene list per pathway
__device__ int   g_ng[P_];                    // active gene count per pathway
__device__ int   g_ecnt[P_];                  // samples routed to each expert
__device__ int   g_eb[P_ * B_];               // sample index
__device__ int   g_eslot[P_ * B_];            // topk slot (0..2)
__device__ float g_ew[P_ * B_];               // gate weight (sigmoid)
__device__ float g_contrib[B_ * 3 * O_];      // weighted expert outputs per (b,slot)

// ---------------- kernel 1: gate hidden GEMM (k-split) ----------------
// grid (KSPLIT, 8), 256 threads. Block computes 32 samples x 128 hidden over 250 k.
__global__ __launch_bounds__(256) void k_gate1(const float* __restrict__ x_rna,
                                               const float* __restrict__ gw1) {
    const int ks = blockIdx.x;
    const int sb = blockIdx.y;
    const int t  = threadIdx.x;
    __shared__ float xs[32 * KC];
    const int k0 = ks * KC;

    for (int i = t; i < 32 * KC; i += 256) {
        int s = i / KC;
        int k = i - s * KC;
        xs[i] = x_rna[(sb * 32 + s) * G_ + k0 + k];
    }
    __syncthreads();

    const int hq = t & 31;     // h quad: h0 = hq*4
    const int sg = t >> 5;     // sample group: 4 samples
    float acc[4][4];
#pragma unroll
    for (int i = 0; i < 4; i++)
#pragma unroll
        for (int j = 0; j < 4; j++) acc[i][j] = 0.f;

    const float* wp = gw1 + (size_t)k0 * GH_ + hq * 4;
    const float* xp = xs + sg * 4 * KC;

    for (int k = 0; k < KC; k++) {
        float4 w = *(const float4*)(wp + (size_t)k * GH_);
#pragma unroll
        for (int i = 0; i < 4; i++) {
            float xv = xp[i * KC + k];
            acc[i][0] = fmaf(xv, w.x, acc[i][0]);
            acc[i][1] = fmaf(xv, w.y, acc[i][1]);
            acc[i][2] = fmaf(xv, w.z, acc[i][2]);
            acc[i][3] = fmaf(xv, w.w, acc[i][3]);
        }
    }
#pragma unroll
    for (int i = 0; i < 4; i++) {
        int b = sb * 32 + sg * 4 + i;
        float4 v = make_float4(acc[i][0], acc[i][1], acc[i][2], acc[i][3]);
        *(float4*)&g_part[(size_t)(ks * B_ + b) * GH_ + hq * 4] = v;
    }
}

// ---------------- kernel 2: mask compaction (ordered) + counter zero ----------------
// grid P_, 32 threads (1 warp). Warp-ballot compaction preserves gene order.
__global__ __launch_bounds__(32) void k_mask(const float* __restrict__ mask) {
    const int p = blockIdx.x;
    const int lane = threadIdx.x;
    int base = 0;
    for (int g0 = 0; g0 < G_; g0 += 32) {
        float m = mask[(size_t)(g0 + lane) * P_ + p];
        unsigned bal = __ballot_sync(0xffffffffu, m != 0.0f);
        if (m != 0.0f)
            g_glist[p * G_ + base + __popc(bal & ((1u << lane) - 1u))] = g0 + lane;
        base += __popc(bal);
    }
    if (lane == 0) { g_ng[p] = base; g_ecnt[p] = 0; }
}

// ---------------- kernel 3: reduce + logits + top3 + routing ----------------
// grid B_, 128 threads.
__global__ __launch_bounds__(128) void k_gate2(const float* __restrict__ gb1,
                                               const float* __restrict__ gw2,
                                               const float* __restrict__ gb2,
                                               float* __restrict__ d_out) {
    const int b = blockIdx.x;
    const int t = threadIdx.x;
    __shared__ float sh[GH_];
    __shared__ float av[P_], cv[P_];
    __shared__ int   ci[P_];
    __shared__ float bestv[3];
    __shared__ int   besti[3];

    float s = 0.f;
#pragma unroll
    for (int ks = 0; ks < KSPLIT; ks++)
        s += g_part[(size_t)(ks * B_ + b) * GH_ + t];
    s += gb1[t];
    sh[t] = fmaxf(s, 0.f);
    __syncthreads();

    float lg = gb2[t];
#pragma unroll 4
    for (int h = 0; h < GH_; h++)
        lg = fmaf(sh[h], gw2[h * P_ + t], lg);
    av[t] = lg;
    __syncthreads();

    // exact top-3; ties -> lower index (matches lax.top_k stability)
    for (int r = 0; r < 3; r++) {
        cv[t] = av[t]; ci[t] = t;
        __syncthreads();
        for (int w = 64; w > 0; w >>= 1) {
            if (t < w) {
                float v2 = cv[t + w]; int i2 = ci[t + w];
                if (v2 > cv[t] || (v2 == cv[t] && i2 < ci[t])) { cv[t] = v2; ci[t] = i2; }
            }
            __syncthreads();
        }
        if (t == 0) { bestv[r] = cv[0]; besti[r] = ci[0]; }
        __syncthreads();
        if (t == besti[r]) av[t] = -INFINITY;
        __syncthreads();
    }

    float gw = 0.f;
#pragma unroll
    for (int r = 0; r < 3; r++)
        if (t == besti[r]) gw = 1.f / (1.f + expf(-bestv[r]));
    d_out[B_ * C_ + b * P_ + t] = gw;   // gate_weights region after logits

    if (t < 3) {
        int p = besti[t];
        float wv = 1.f / (1.f + expf(-bestv[t]));
        int pos = atomicAdd(&g_ecnt[p], 1);
        g_eb[p * B_ + pos]    = b;
        g_eslot[p * B_ + pos] = t;
        g_ew[p * B_ + pos]    = wv;
    }
}

// ---------------- kernel 4: sparse experts ----------------
// grid (P_, 8), 256 threads. Block = (expert p, sample chunk of 8).
// Only mask-active W1 rows are read; 2 samples packed per fma.rn.f32x2.
__global__ __launch_bounds__(256) void k_expert(const float* __restrict__ xr,
                                                const float* __restrict__ xc,
                                                const float* __restrict__ xm,
                                                const float* __restrict__ W1,
                                                const float* __restrict__ b1,
                                                const float* __restrict__ bn_g,
                                                const float* __restrict__ bn_b,
                                                const float* __restrict__ bn_m,
                                                const float* __restrict__ bn_v,
                                                const float* __restrict__ W2,
                                                const float* __restrict__ b2) {
    const int p = blockIdx.x;
    const int cnt = g_ecnt[p];
    if (cnt == 0) return;                       // uniform across block
    const int t = threadIdx.x;

    __shared__ float W2s[H_ * O_];
    __shared__ float scs[H_], offs[H_], b2s[O_];
    __shared__ int   sgl[TG];
    __shared__ __align__(16) float xs[3 * TG * 8];   // xs[o][j][s]
    __shared__ float red[8 * H_ * 9];                // [grp][h][s] padded
    __shared__ float hfm[8 * H_];
    __shared__ int   sb_b[8], sb_slot[8];
    __shared__ float sb_w[8];

    for (int i = t; i < H_ * O_; i += 256) W2s[i] = W2[p * H_ * O_ + i];
    if (t < H_) {
        float sc = bn_g[p * H_ + t] * rsqrtf(bn_v[p * H_ + t] + EPS_);
        scs[t]  = sc;
        offs[t] = (b1[p * H_ + t] - bn_m[p * H_ + t]) * sc + bn_b[p * H_ + t];
    }
    if (t < O_) b2s[t] = b2[p * O_ + t];
    const int ng = g_ng[p];
    const int hp  = t & 31;    // h pair: h0 = 2*hp
    const int grp = t >> 5;    // 8 row-groups

    for (int cs = blockIdx.y * 8; cs < cnt; cs += 64) {
        const int scn = min(8, cnt - cs);
        __syncthreads();        // prev chunk's smem consumers done
        if (t < 8) {
            int idx = cs + ((t < scn) ? t : 0);
            sb_b[t]    = g_eb[p * B_ + idx];
            sb_slot[t] = g_eslot[p * B_ + idx];
            sb_w[t]    = g_ew[p * B_ + idx];
        }

        unsigned long long acc[2][4];
#pragma unroll
        for (int a = 0; a < 2; a++)
#pragma unroll
            for (int q = 0; q < 4; q++) acc[a][q] = 0ULL;

        for (int gt = 0; gt < ng; gt += TG) {
            const int tg = min(TG, ng - gt);
            __syncthreads();    // entries staged / prev compute done reading xs,sgl
            if (t < tg) sgl[t] = g_glist[p * G_ + gt + t];
            __syncthreads();
            // gather x (L2-resident: x tensors total 12 MB, reused by all experts)
            for (int i = t; i < 3 * TG * 8; i += 256) {
                int s = i & 7, j = (i >> 3) & (TG - 1), o = i >> 10;
                if (j < tg) {
                    int bb = sb_b[(s < scn) ? s : 0];
                    const float* xp = (o == 0) ? xr : ((o == 1) ? xc : xm);
                    xs[i] = xp[(size_t)bb * G_ + sgl[j]];
                }
            }
            __syncthreads();
            // compute: only active rows of W1 touched
#pragma unroll
            for (int o = 0; o < 3; o++) {
                const float* Wp = W1 + ((size_t)p * D_ + o * G_) * H_;
                for (int j = grp; j < tg; j += 8) {
                    int gene = sgl[j];
                    const float2 wv = *(const float2*)(Wp + (size_t)gene * H_ + 2 * hp);
                    unsigned long long w0, w1;
                    asm("mov.b64 %0, {%1,%1};" : "=l"(w0) : "r"(__float_as_uint(wv.x)));
                    asm("mov.b64 %0, {%1,%1};" : "=l"(w1) : "r"(__float_as_uint(wv.y)));
                    const unsigned long long* xv =
                        (const unsigned long long*)&xs[(o * TG + j) * 8];
#pragma unroll
                    for (int sp = 0; sp < 4; sp++) {
                        unsigned long long x2 = xv[sp];
                        asm("fma.rn.f32x2 %0, %1, %2, %0;" : "+l"(acc[0][sp]) : "l"(x2), "l"(w0));
                        asm("fma.rn.f32x2 %0, %1, %2, %0;" : "+l"(acc[1][sp]) : "l"(x2), "l"(w1));
                    }
                }
            }
        }
        // spill per-group partials
#pragma unroll
        for (int hl = 0; hl < 2; hl++)
#pragma unroll
            for (int sp = 0; sp < 4; sp++) {
                unsigned lo, hi;
                asm("mov.b64 {%0,%1}, %2;" : "=r"(lo), "=r"(hi) : "l"(acc[hl][sp]));
                int h = 2 * hp + hl;
                red[(grp * H_ + h) * 9 + 2 * sp]     = __uint_as_float(lo);
                red[(grp * H_ + h) * 9 + 2 * sp + 1] = __uint_as_float(hi);
            }
        __syncthreads();
        // cross-group reduce + BN(eval) + ReLU
        {
            int h = t & 63, s0 = t >> 6;
#pragma unroll
            for (int q = 0; q < 2; q++) {
                int s = s0 + 4 * q;
                float v = 0.f;
#pragma unroll
                for (int g8 = 0; g8 < 8; g8++) v += red[(g8 * H_ + h) * 9 + s];
                hfm[s * H_ + h] = fmaxf(fmaf(v, scs[h], offs[h]), 0.f);
            }
        }
        __syncthreads();
        // h @ W2 + b2, weight, scatter to (b,slot)
        if (t < 8 * O_) {
            int s = t >> 4, o = t & 15;
            if (s < scn) {
                float v = b2s[o];
#pragma unroll 8
                for (int h = 0; h < H_; h++) v = fmaf(hfm[s * H_ + h], W2s[h * O_ + o], v);
                g_contrib[(sb_b[s] * 3 + sb_slot[s]) * O_ + o] = sb_w[s] * v;
            }
        }
    }
}

// ---------------- kernel 5: slot-sum + classifier ----------------
__global__ __launch_bounds__(256) void k_final(const float* __restrict__ cw1,
                                               const float* __restrict__ cb1,
                                               const float* __restrict__ cw2,
                                               const float* __restrict__ cb2,
                                               float* __restrict__ d_out) {
    const int b = threadIdx.x;
    if (b >= B_) return;
    float feat[O_];
#pragma unroll
    for (int o = 0; o < O_; o++)
        feat[o] = g_contrib[(b * 3 + 0) * O_ + o]
                + g_contrib[(b * 3 + 1) * O_ + o]
                + g_contrib[(b * 3 + 2) * O_ + o];
    float hid[CH_];
#pragma unroll
    for (int ch = 0; ch < CH_; ch++) {
        float v = cb1[ch];
#pragma unroll
        for (int o = 0; o < O_; o++) v = fmaf(feat[o], cw1[o * CH_ + ch], v);
        hid[ch] = fmaxf(v, 0.f);
    }
#pragma unroll
    for (int c = 0; c < C_; c++) {
        float v = cb2[c];
#pragma unroll
        for (int ch = 0; ch < CH_; ch++) v = fmaf(hid[ch], cw2[ch * C_ + c], v);
        d_out[b * C_ + c] = v;
    }
}

// ---------------- launch ----------------
extern "C" void kernel_launch(void* const* d_in, const int* in_sizes, int n_in,
                              void* d_out, int out_size) {
    const float* x_rna    = (const float*)d_in[0];
    const float* x_cnv    = (const float*)d_in[1];
    const float* x_met    = (const float*)d_in[2];
    const float* gene_mask= (const float*)d_in[3];
    const float* gate_w1  = (const float*)d_in[4];
    const float* gate_b1  = (const float*)d_in[5];
    const float* gate_w2  = (const float*)d_in[6];
    const float* gate_b2  = (const float*)d_in[7];
    const float* W1       = (const float*)d_in[8];
    const float* b1       = (const float*)d_in[9];
    const float* bn_gamma = (const float*)d_in[10];
    const float* bn_beta  = (const float*)d_in[11];
    const float* bn_mean  = (const float*)d_in[12];
    const float* bn_var   = (const float*)d_in[13];
    const float* W2       = (const float*)d_in[14];
    const float* b2       = (const float*)d_in[15];
    const float* cls_w1   = (const float*)d_in[16];
    const float* cls_b1   = (const float*)d_in[17];
    const float* cls_w2   = (const float*)d_in[18];
    const float* cls_b2   = (const float*)d_in[19];
    float* out = (float*)d_out;

    k_gate1 <<<dim3(KSPLIT, 8), 256>>>(x_rna, gate_w1);
    k_mask  <<<P_, 32>>>(gene_mask);
    k_gate2 <<<B_, 128>>>(gate_b1, gate_w2, gate_b2, out);
    k_expert<<<dim3(P_, 8), 256>>>(x_rna, x_cnv, x_met, W1, b1,
                                   bn_gamma, bn_beta, bn_mean, bn_var, W2, b2);
    k_final <<<1, 256>>>(cls_w1, cls_b1, cls_w2, cls_b2, out);
}

// round 6
// speedup vs baseline: 1.3049x; 1.3049x over previous
#include <cuda_runtime.h>
#include <math.h>

#define B_  256
#define G_  4000
#define P_  128
#define H_  64
#define O_  16
#define GH_ 128
#define CH_ 8
#define C_  5
#define D_  12000
#define KSPLIT 16
#define KC 250        // G_/KSPLIT
#define NT  16        // gene tiles per expert in phase A
#define EPS_ 1e-5f

typedef unsigned long long ull;

// ---------------- scratch (__device__ globals; no allocs) ----------------
__device__ float g_part[KSPLIT * B_ * GH_];    // gate hidden partials [ks][b][h]
__device__ int   g_glist[P_ * G_];             // active gene list per pathway
__device__ int   g_ng[P_];                     // active gene count per pathway
__device__ int   g_ecnt[P_];                   // samples routed to each expert
__device__ int   g_eb[P_ * B_];                // sample index per routed entry
__device__ int   g_ebslot[P_ * B_];            // b*3+slot per routed entry
__device__ int   g_bp[B_ * 3];                 // expert id per (b,slot)
__device__ float g_bw[B_ * 3];                 // gate weight per (b,slot)
__device__ float g_hpart[B_ * 3 * NT * H_];    // partial h sums [bslot][tile][h]

// ---------------- kernel 1: gate hidden GEMM (k-split, f32x2 packed) ----------------
// grid (KSPLIT, 8), 256 threads. Block: 32 samples x 128 hidden over 250 k.
__global__ __launch_bounds__(256) void k_gate1(const float* __restrict__ x_rna,
                                               const float* __restrict__ gw1) {
    const int ks = blockIdx.x;
    const int sb = blockIdx.y;
    const int t  = threadIdx.x;
    const int k0 = ks * KC;
    __shared__ float xs[KC * 34];   // [k][s] padded to 34 (bank + 8B align)

    {   // stage x: warp w covers samples {w, w+8, w+16, w+24}; lanes over k
        const int w = t >> 5, lane = t & 31;
#pragma unroll
        for (int si = 0; si < 4; si++) {
            int s = w + si * 8;
            const float* xp = x_rna + (size_t)(sb * 32 + s) * G_ + k0;
            for (int k = lane; k < KC; k += 32)
                xs[k * 34 + s] = xp[k];
        }
    }
    __syncthreads();

    const int hq = t & 31;     // 4 h cols: hq*4
    const int sg = t >> 5;     // 8 groups x 4 samples
    const int s0 = sg * 4;

    ull acc[4][2];
#pragma unroll
    for (int i = 0; i < 4; i++) { acc[i][0] = 0ULL; acc[i][1] = 0ULL; }

    const float* wp = gw1 + (size_t)k0 * GH_ + hq * 4;
#pragma unroll 2
    for (int k = 0; k < KC; k++) {
        float4 w = *(const float4*)(wp + (size_t)k * GH_);
        ull x01 = *(const ull*)&xs[k * 34 + s0];
        ull x23 = *(const ull*)&xs[k * 34 + s0 + 2];
        ull wb0, wb1, wb2, wb3;
        asm("mov.b64 %0, {%1,%1};" : "=l"(wb0) : "r"(__float_as_uint(w.x)));
        asm("mov.b64 %0, {%1,%1};" : "=l"(wb1) : "r"(__float_as_uint(w.y)));
        asm("mov.b64 %0, {%1,%1};" : "=l"(wb2) : "r"(__float_as_uint(w.z)));
        asm("mov.b64 %0, {%1,%1};" : "=l"(wb3) : "r"(__float_as_uint(w.w)));
        asm("fma.rn.f32x2 %0, %1, %2, %0;" : "+l"(acc[0][0]) : "l"(x01), "l"(wb0));
        asm("fma.rn.f32x2 %0, %1, %2, %0;" : "+l"(acc[1][0]) : "l"(x01), "l"(wb1));
        asm("fma.rn.f32x2 %0, %1, %2, %0;" : "+l"(acc[2][0]) : "l"(x01), "l"(wb2));
        asm("fma.rn.f32x2 %0, %1, %2, %0;" : "+l"(acc[3][0]) : "l"(x01), "l"(wb3));
        asm("fma.rn.f32x2 %0, %1, %2, %0;" : "+l"(acc[0][1]) : "l"(x23), "l"(wb0));
        asm("fma.rn.f32x2 %0, %1, %2, %0;" : "+l"(acc[1][1]) : "l"(x23), "l"(wb1));
        asm("fma.rn.f32x2 %0, %1, %2, %0;" : "+l"(acc[2][1]) : "l"(x23), "l"(wb2));
        asm("fma.rn.f32x2 %0, %1, %2, %0;" : "+l"(acc[3][1]) : "l"(x23), "l"(wb3));
    }

    // unpack and store 4 samples x float4
    float v[4][2][2];   // [hc][sp][lo/hi]
#pragma unroll
    for (int hc = 0; hc < 4; hc++)
#pragma unroll
        for (int sp = 0; sp < 2; sp++) {
            unsigned lo, hi;
            asm("mov.b64 {%0,%1}, %2;" : "=r"(lo), "=r"(hi) : "l"(acc[hc][sp]));
            v[hc][sp][0] = __uint_as_float(lo);
            v[hc][sp][1] = __uint_as_float(hi);
        }
#pragma unroll
    for (int sp = 0; sp < 2; sp++)
#pragma unroll
        for (int sg2 = 0; sg2 < 2; sg2++) {
            int s = s0 + 2 * sp + sg2;
            float4 o4 = make_float4(v[0][sp][sg2], v[1][sp][sg2], v[2][sp][sg2], v[3][sp][sg2]);
            *(float4*)&g_part[(size_t)(ks * B_ + sb * 32 + s) * GH_ + hq * 4] = o4;
        }
}

// ---------------- kernel 2: mask compaction (4 warps + prefetch) ----------------
// grid P_, 128 threads. Warp q handles genes [q*1024, min(4000,(q+1)*1024)).
__global__ __launch_bounds__(128) void k_mask(const float* __restrict__ mask) {
    const int p = blockIdx.x;
    const int t = threadIdx.x;
    const int q = t >> 5, lane = t & 31;
    __shared__ int qlist[4][1024];
    __shared__ int qcnt[4];
    __shared__ int qoff[4];

    const int gstart = q * 1024;
    const int gend   = min(G_, gstart + 1024);
    const int niter  = (gend - gstart) >> 5;   // 32,32,32,29
    int base = 0;
    const unsigned lm = (1u << lane) - 1u;

    for (int it = 0; it < niter; it += 4) {
        float m[4];
#pragma unroll
        for (int u = 0; u < 4; u++) {
            int iu = it + u;
            m[u] = (iu < niter) ? mask[(size_t)(gstart + iu * 32 + lane) * P_ + p] : 0.0f;
        }
#pragma unroll
        for (int u = 0; u < 4; u++) {
            int iu = it + u;
            if (iu < niter) {
                unsigned bal = __ballot_sync(0xffffffffu, m[u] != 0.0f);
                if (m[u] != 0.0f)
                    qlist[q][base + __popc(bal & lm)] = gstart + iu * 32 + lane;
                base += __popc(bal);
            }
        }
    }
    if (lane == 0) qcnt[q] = base;
    __syncthreads();
    if (t == 0) {
        int s = 0;
#pragma unroll
        for (int i = 0; i < 4; i++) { qoff[i] = s; s += qcnt[i]; }
        g_ng[p] = s;
        g_ecnt[p] = 0;
    }
    __syncthreads();
    for (int i = lane; i < qcnt[q]; i += 32)
        g_glist[p * G_ + qoff[q] + i] = qlist[q][i];
}

// ---------------- kernel 3: reduce + logits + top3 + routing ----------------
// grid B_, 128 threads.
__global__ __launch_bounds__(128) void k_gate2(const float* __restrict__ gb1,
                                               const float* __restrict__ gw2,
                                               const float* __restrict__ gb2,
                                               float* __restrict__ d_out) {
    const int b = blockIdx.x;
    const int t = threadIdx.x;
    __shared__ float sh[GH_];
    __shared__ float av[P_], cv[P_];
    __shared__ int   ci[P_];
    __shared__ float bestv[3];
    __shared__ int   besti[3];

    float s = 0.f;
#pragma unroll
    for (int ks = 0; ks < KSPLIT; ks++)
        s += g_part[(size_t)(ks * B_ + b) * GH_ + t];
    s += gb1[t];
    sh[t] = fmaxf(s, 0.f);
    __syncthreads();

    float lg = gb2[t];
#pragma unroll 4
    for (int h = 0; h < GH_; h++)
        lg = fmaf(sh[h], gw2[h * P_ + t], lg);
    av[t] = lg;
    __syncthreads();

    for (int r = 0; r < 3; r++) {
        cv[t] = av[t]; ci[t] = t;
        __syncthreads();
        for (int w = 64; w > 0; w >>= 1) {
            if (t < w) {
                float v2 = cv[t + w]; int i2 = ci[t + w];
                if (v2 > cv[t] || (v2 == cv[t] && i2 < ci[t])) { cv[t] = v2; ci[t] = i2; }
            }
            __syncthreads();
        }
        if (t == 0) { bestv[r] = cv[0]; besti[r] = ci[0]; }
        __syncthreads();
        if (t == besti[r]) av[t] = -INFINITY;
        __syncthreads();
    }

    float gw = 0.f;
#pragma unroll
    for (int r = 0; r < 3; r++)
        if (t == besti[r]) gw = 1.f / (1.f + expf(-bestv[r]));
    d_out[B_ * C_ + b * P_ + t] = gw;   // gate_weights after logits

    if (t < 3) {
        int p = besti[t];
        float wv = 1.f / (1.f + expf(-bestv[t]));
        int pos = atomicAdd(&g_ecnt[p], 1);
        g_eb[p * B_ + pos]     = b;
        g_ebslot[p * B_ + pos] = b * 3 + t;
        g_bp[b * 3 + t] = p;
        g_bw[b * 3 + t] = wv;
    }
}

// ---------------- kernel 4a: sparse expert partial-h ----------------
// grid (P_, NT), 256 threads. Block = (expert p, gene tile ti).
// Writes partial h sums for every routed sample of p into g_hpart[bslot][ti][h].
__global__ __launch_bounds__(256) void k_expertA(const float* __restrict__ xr,
                                                 const float* __restrict__ xc,
                                                 const float* __restrict__ xm,
                                                 const float* __restrict__ W1) {
    const int p  = blockIdx.x;
    const int ti = blockIdx.y;
    const int cnt = g_ecnt[p];
    if (cnt == 0) return;
    const int ng  = g_ng[p];
    const int ng3 = 3 * ng;
    const int r0 = (ng3 * ti) / NT;
    const int r1 = (ng3 * (ti + 1)) / NT;
    const int t = threadIdx.x;
    const int hg = t & 15;     // 4 h cols: hg*4
    const int rg = t >> 4;     // 16 row groups

    __shared__ int sgo[128];                       // (o<<16)|gene per row
    __shared__ __align__(16) float xs[128 * 8];    // [row][sample]
    __shared__ float red[8 * H_ * 17];             // [s][h][rg pad 17]
    __shared__ int sb_b[8], sb_bslot[8];

    for (int cs = 0; cs < cnt; cs += 8) {
        const int scn = min(8, cnt - cs);
        __syncthreads();
        if (t < 8) {
            int idx = cs + ((t < scn) ? t : 0);
            sb_b[t]     = g_eb[p * B_ + idx];
            sb_bslot[t] = g_ebslot[p * B_ + idx];
        }

        ull acc[4][4];
#pragma unroll
        for (int a = 0; a < 4; a++)
#pragma unroll
            for (int sp = 0; sp < 4; sp++) acc[a][sp] = 0ULL;

        for (int rb = r0; rb < r1; rb += 128) {
            const int nr = min(128, r1 - rb);
            __syncthreads();
            if (t < nr) {
                int r = rb + t;
                int o = r / ng;
                int gene = g_glist[p * G_ + (r - o * ng)];
                sgo[t] = (o << 16) | gene;
            }
            __syncthreads();
            // gather x[row][sample] (L2 resident)
            for (int i = t; i < nr * 8; i += 256) {
                int j = i >> 3, s = i & 7;
                int code = sgo[j];
                int o = code >> 16, gene = code & 0xFFFF;
                const float* xp = (o == 0) ? xr : ((o == 1) ? xc : xm);
                xs[i] = xp[(size_t)sb_b[s] * G_ + gene];
            }
            __syncthreads();
            // compute: one LDG.128 of W1 per row per thread, f32x2 packed fma
            for (int j = rg; j < nr; j += 16) {
                int code = sgo[j];
                int o = code >> 16, gene = code & 0xFFFF;
                const float4 w = *(const float4*)(W1 + ((size_t)p * D_ + o * G_ + gene) * H_ + hg * 4);
                ull wb0, wb1, wb2, wb3;
                asm("mov.b64 %0, {%1,%1};" : "=l"(wb0) : "r"(__float_as_uint(w.x)));
                asm("mov.b64 %0, {%1,%1};" : "=l"(wb1) : "r"(__float_as_uint(w.y)));
                asm("mov.b64 %0, {%1,%1};" : "=l"(wb2) : "r"(__float_as_uint(w.z)));
                asm("mov.b64 %0, {%1,%1};" : "=l"(wb3) : "r"(__float_as_uint(w.w)));
                const ull* xv = (const ull*)&xs[j * 8];
#pragma unroll
                for (int sp = 0; sp < 4; sp++) {
                    ull x2 = xv[sp];
                    asm("fma.rn.f32x2 %0, %1, %2, %0;" : "+l"(acc[0][sp]) : "l"(x2), "l"(wb0));
                    asm("fma.rn.f32x2 %0, %1, %2, %0;" : "+l"(acc[1][sp]) : "l"(x2), "l"(wb1));
                    asm("fma.rn.f32x2 %0, %1, %2, %0;" : "+l"(acc[2][sp]) : "l"(x2), "l"(wb2));
                    asm("fma.rn.f32x2 %0, %1, %2, %0;" : "+l"(acc[3][sp]) : "l"(x2), "l"(wb3));
                }
            }
        }
        // unpack accs into red[s][h][rg]
        __syncthreads();
#pragma unroll
        for (int hc = 0; hc < 4; hc++)
#pragma unroll
            for (int sp = 0; sp < 4; sp++) {
                unsigned lo, hi;
                asm("mov.b64 {%0,%1}, %2;" : "=r"(lo), "=r"(hi) : "l"(acc[hc][sp]));
                int h = hg * 4 + hc;
                red[((2 * sp) * H_ + h) * 17 + rg]     = __uint_as_float(lo);
                red[((2 * sp + 1) * H_ + h) * 17 + rg] = __uint_as_float(hi);
            }
        __syncthreads();
        // reduce 16 row-groups, write partials
#pragma unroll
        for (int rep = 0; rep < 2; rep++) {
            int v = t + rep * 256;
            int h = v & 63, s = v >> 6;
            float sum = 0.f;
#pragma unroll
            for (int g16 = 0; g16 < 16; g16++)
                sum += red[(s * H_ + h) * 17 + g16];
            if (s < scn)
                g_hpart[(size_t)sb_bslot[s] * (NT * H_) + ti * H_ + h] = sum;
        }
    }
}

// ---------------- kernel 4b: tile-sum + BN + ReLU + W2 + gate + classifier ----------------
// grid B_, 192 threads (3 slots x 64 h).
__global__ __launch_bounds__(192) void k_post(const float* __restrict__ b1,
                                              const float* __restrict__ bn_g,
                                              const float* __restrict__ bn_b,
                                              const float* __restrict__ bn_m,
                                              const float* __restrict__ bn_v,
                                              const float* __restrict__ W2,
                                              const float* __restrict__ b2,
                                              const float* __restrict__ cw1,
                                              const float* __restrict__ cb1,
                                              const float* __restrict__ cw2,
                                              const float* __restrict__ cb2,
                                              float* __restrict__ d_out) {
    const int b = blockIdx.x;
    const int t = threadIdx.x;
    const int slot = t >> 6, h = t & 63;
    __shared__ float hfm[3][H_];
    __shared__ float sfeat[3 * O_];
    __shared__ float feat[O_];
    __shared__ float hid[CH_];

    {
        int bslot = b * 3 + slot;
        int p = g_bp[bslot];
        float v = 0.f;
#pragma unroll
        for (int ti = 0; ti < NT; ti++)
            v += g_hpart[(size_t)bslot * (NT * H_) + ti * H_ + h];
        float sc  = bn_g[p * H_ + h] * rsqrtf(bn_v[p * H_ + h] + EPS_);
        float off = (b1[p * H_ + h] - bn_m[p * H_ + h]) * sc + bn_b[p * H_ + h];
        hfm[slot][h] = fmaxf(fmaf(v, sc, off), 0.f);
    }
    __syncthreads();
    if (t < 3 * O_) {
        int sl = t >> 4, o = t & 15;
        int bslot = b * 3 + sl;
        int p = g_bp[bslot];
        float a = b2[p * O_ + o];
#pragma unroll 8
        for (int hh = 0; hh < H_; hh++)
            a = fmaf(hfm[sl][hh], W2[(p * H_ + hh) * O_ + o], a);
        sfeat[t] = g_bw[bslot] * a;
    }
    __syncthreads();
    if (t < O_)
        feat[t] = sfeat[t] + sfeat[O_ + t] + sfeat[2 * O_ + t];
    __syncthreads();
    if (t < CH_) {
        float v = cb1[t];
#pragma unroll
        for (int o = 0; o < O_; o++) v = fmaf(feat[o], cw1[o * CH_ + t], v);
        hid[t] = fmaxf(v, 0.f);
    }
    __syncthreads();
    if (t < C_) {
        float v = cb2[t];
#pragma unroll
        for (int ch = 0; ch < CH_; ch++) v = fmaf(hid[ch], cw2[ch * C_ + t], v);
        d_out[b * C_ + t] = v;
    }
}

// ---------------- launch ----------------
extern "C" void kernel_launch(void* const* d_in, const int* in_sizes, int n_in,
                              void* d_out, int out_size) {
    const float* x_rna    = (const float*)d_in[0];
    const float* x_cnv    = (const float*)d_in[1];
    const float* x_met    = (const float*)d_in[2];
    const float* gene_mask= (const float*)d_in[3];
    const float* gate_w1  = (const float*)d_in[4];
    const float* gate_b1  = (const float*)d_in[5];
    const float* gate_w2  = (const float*)d_in[6];
    const float* gate_b2  = (const float*)d_in[7];
    const float* W1       = (const float*)d_in[8];
    const float* b1       = (const float*)d_in[9];
    const float* bn_gamma = (const float*)d_in[10];
    const float* bn_beta  = (const float*)d_in[11];
    const float* bn_mean  = (const float*)d_in[12];
    const float* bn_var   = (const float*)d_in[13];
    const float* W2       = (const float*)d_in[14];
    const float* b2       = (const float*)d_in[15];
    const float* cls_w1   = (const float*)d_in[16];
    const float* cls_b1   = (const float*)d_in[17];
    const float* cls_w2   = (const float*)d_in[18];
    const float* cls_b2   = (const float*)d_in[19];
    float* out = (float*)d_out;

    k_gate1  <<<dim3(KSPLIT, 8), 256>>>(x_rna, gate_w1);
    k_mask   <<<P_, 128>>>(gene_mask);
    k_gate2  <<<B_, 128>>>(gate_b1, gate_w2, gate_b2, out);
    k_expertA<<<dim3(P_, NT), 256>>>(x_rna, x_cnv, x_met, W1);
    k_post   <<<B_, 192>>>(b1, bn_gamma, bn_beta, bn_mean, bn_var, W2, b2,
                           cls_w1, cls_b1, cls_w2, cls_b2, out);
}

// round 12
// speedup vs baseline: 1.3392x; 1.0263x over previous
#include <cuda_runtime.h>
#include <math.h>

#define B_  256
#define G_  4000
#define P_  128
#define H_  64
#define O_  16
#define GH_ 128
#define CH_ 8
#define C_  5
#define D_  12000
#define KSPLIT 16
#define KC 250        // G_/KSPLIT
#define NT  16        // gene tiles per expert in phase A
#define SCMAX 32      // max sample chunks (32*8 = 256 samples)
#define EPS_ 1e-5f

typedef unsigned long long ull;

// ---------------- scratch (__device__ globals; no allocs) ----------------
__device__ float g_part[KSPLIT * B_ * GH_];    // gate hidden partials [ks][b][h]
__device__ int   g_glist[P_ * G_];             // active gene list per pathway
__device__ int   g_ng[P_];                     // active gene count per pathway
__device__ int   g_ecnt[P_];                   // samples routed to each expert
__device__ int   g_eb[P_ * B_];                // sample index per routed entry
__device__ int   g_ebslot[P_ * B_];            // b*3+slot per routed entry
__device__ int   g_bp[B_ * 3];                 // expert id per (b,slot)
__device__ float g_bw[B_ * 3];                 // gate weight per (b,slot)
__device__ float g_hpart[B_ * 3 * NT * H_];    // partial h sums [bslot][tile][h]

// ---------------- kernel 1: gate hidden GEMM (k-split, f32x2 packed) ----------------
// grid (KSPLIT, 8), 256 threads. Block: 32 samples x 128 hidden over 250 k.
__global__ __launch_bounds__(256) void k_gate1(const float* __restrict__ x_rna,
                                               const float* __restrict__ gw1) {
    const int ks = blockIdx.x;
    const int sb = blockIdx.y;
    const int t  = threadIdx.x;
    const int k0 = ks * KC;
    __shared__ float xs[KC * 34];   // [k][s] padded to 34 (bank + 8B align)

    {   // stage x: warp w covers samples {w, w+8, w+16, w+24}; lanes over k
        const int w = t >> 5, lane = t & 31;
#pragma unroll
        for (int si = 0; si < 4; si++) {
            int s = w + si * 8;
            const float* xp = x_rna + (size_t)(sb * 32 + s) * G_ + k0;
            for (int k = lane; k < KC; k += 32)
                xs[k * 34 + s] = xp[k];
        }
    }
    __syncthreads();

    const int hq = t & 31;     // 4 h cols: hq*4
    const int sg = t >> 5;     // 8 groups x 4 samples
    const int s0 = sg * 4;

    ull acc[4][2];
#pragma unroll
    for (int i = 0; i < 4; i++) { acc[i][0] = 0ULL; acc[i][1] = 0ULL; }

    const float* wp = gw1 + (size_t)k0 * GH_ + hq * 4;
#pragma unroll 2
    for (int k = 0; k < KC; k++) {
        float4 w = *(const float4*)(wp + (size_t)k * GH_);
        ull x01 = *(const ull*)&xs[k * 34 + s0];
        ull x23 = *(const ull*)&xs[k * 34 + s0 + 2];
        ull wb0, wb1, wb2, wb3;
        asm("mov.b64 %0, {%1,%1};" : "=l"(wb0) : "r"(__float_as_uint(w.x)));
        asm("mov.b64 %0, {%1,%1};" : "=l"(wb1) : "r"(__float_as_uint(w.y)));
        asm("mov.b64 %0, {%1,%1};" : "=l"(wb2) : "r"(__float_as_uint(w.z)));
        asm("mov.b64 %0, {%1,%1};" : "=l"(wb3) : "r"(__float_as_uint(w.w)));
        asm("fma.rn.f32x2 %0, %1, %2, %0;" : "+l"(acc[0][0]) : "l"(x01), "l"(wb0));
        asm("fma.rn.f32x2 %0, %1, %2, %0;" : "+l"(acc[1][0]) : "l"(x01), "l"(wb1));
        asm("fma.rn.f32x2 %0, %1, %2, %0;" : "+l"(acc[2][0]) : "l"(x01), "l"(wb2));
        asm("fma.rn.f32x2 %0, %1, %2, %0;" : "+l"(acc[3][0]) : "l"(x01), "l"(wb3));
        asm("fma.rn.f32x2 %0, %1, %2, %0;" : "+l"(acc[0][1]) : "l"(x23), "l"(wb0));
        asm("fma.rn.f32x2 %0, %1, %2, %0;" : "+l"(acc[1][1]) : "l"(x23), "l"(wb1));
        asm("fma.rn.f32x2 %0, %1, %2, %0;" : "+l"(acc[2][1]) : "l"(x23), "l"(wb2));
        asm("fma.rn.f32x2 %0, %1, %2, %0;" : "+l"(acc[3][1]) : "l"(x23), "l"(wb3));
    }

    // unpack and store 4 samples x float4
    float v[4][2][2];   // [hc][sp][lo/hi]
#pragma unroll
    for (int hc = 0; hc < 4; hc++)
#pragma unroll
        for (int sp = 0; sp < 2; sp++) {
            unsigned lo, hi;
            asm("mov.b64 {%0,%1}, %2;" : "=r"(lo), "=r"(hi) : "l"(acc[hc][sp]));
            v[hc][sp][0] = __uint_as_float(lo);
            v[hc][sp][1] = __uint_as_float(hi);
        }
#pragma unroll
    for (int sp = 0; sp < 2; sp++)
#pragma unroll
        for (int sg2 = 0; sg2 < 2; sg2++) {
            int s = s0 + 2 * sp + sg2;
            float4 o4 = make_float4(v[0][sp][sg2], v[1][sp][sg2], v[2][sp][sg2], v[3][sp][sg2]);
            *(float4*)&g_part[(size_t)(ks * B_ + sb * 32 + s) * GH_ + hq * 4] = o4;
        }
}

// ---------------- kernel 2: mask compaction (4 warps + prefetch) ----------------
// grid P_, 128 threads. Warp q handles genes [q*1024, min(4000,(q+1)*1024)).
__global__ __launch_bounds__(128) void k_mask(const float* __restrict__ mask) {
    const int p = blockIdx.x;
    const int t = threadIdx.x;
    const int q = t >> 5, lane = t & 31;
    __shared__ int qlist[4][1024];
    __shared__ int qcnt[4];
    __shared__ int qoff[4];

    const int gstart = q * 1024;
    const int gend   = min(G_, gstart + 1024);
    const int niter  = (gend - gstart) >> 5;   // 32,32,32,29
    int base = 0;
    const unsigned lm = (1u << lane) - 1u;

    for (int it = 0; it < niter; it += 4) {
        float m[4];
#pragma unroll
        for (int u = 0; u < 4; u++) {
            int iu = it + u;
            m[u] = (iu < niter) ? mask[(size_t)(gstart + iu * 32 + lane) * P_ + p] : 0.0f;
        }
#pragma unroll
        for (int u = 0; u < 4; u++) {
            int iu = it + u;
            if (iu < niter) {
                unsigned bal = __ballot_sync(0xffffffffu, m[u] != 0.0f);
                if (m[u] != 0.0f)
                    qlist[q][base + __popc(bal & lm)] = gstart + iu * 32 + lane;
                base += __popc(bal);
            }
        }
    }
    if (lane == 0) qcnt[q] = base;
    __syncthreads();
    if (t == 0) {
        int s = 0;
#pragma unroll
        for (int i = 0; i < 4; i++) { qoff[i] = s; s += qcnt[i]; }
        g_ng[p] = s;
        g_ecnt[p] = 0;
    }
    __syncthreads();
    for (int i = lane; i < qcnt[q]; i += 32)
        g_glist[p * G_ + qoff[q] + i] = qlist[q][i];
}

// ---------------- kernel 3: reduce + logits + top3 + routing ----------------
// grid B_, 128 threads.
__global__ __launch_bounds__(128) void k_gate2(const float* __restrict__ gb1,
                                               const float* __restrict__ gw2,
                                               const float* __restrict__ gb2,
                                               float* __restrict__ d_out) {
    const int b = blockIdx.x;
    const int t = threadIdx.x;
    __shared__ float sh[GH_];
    __shared__ float av[P_], cv[P_];
    __shared__ int   ci[P_];
    __shared__ float bestv[3];
    __shared__ int   besti[3];

    float s = 0.f;
#pragma unroll
    for (int ks = 0; ks < KSPLIT; ks++)
        s += g_part[(size_t)(ks * B_ + b) * GH_ + t];
    s += gb1[t];
    sh[t] = fmaxf(s, 0.f);
    __syncthreads();

    float lg = gb2[t];
#pragma unroll 4
    for (int h = 0; h < GH_; h++)
        lg = fmaf(sh[h], gw2[h * P_ + t], lg);
    av[t] = lg;
    __syncthreads();

    for (int r = 0; r < 3; r++) {
        cv[t] = av[t]; ci[t] = t;
        __syncthreads();
        for (int w = 64; w > 0; w >>= 1) {
            if (t < w) {
                float v2 = cv[t + w]; int i2 = ci[t + w];
                if (v2 > cv[t] || (v2 == cv[t] && i2 < ci[t])) { cv[t] = v2; ci[t] = i2; }
            }
            __syncthreads();
        }
        if (t == 0) { bestv[r] = cv[0]; besti[r] = ci[0]; }
        __syncthreads();
        if (t == besti[r]) av[t] = -INFINITY;
        __syncthreads();
    }

    float gw = 0.f;
#pragma unroll
    for (int r = 0; r < 3; r++)
        if (t == besti[r]) gw = 1.f / (1.f + expf(-bestv[r]));
    d_out[B_ * C_ + b * P_ + t] = gw;   // gate_weights after logits

    if (t < 3) {
        int p = besti[t];
        float wv = 1.f / (1.f + expf(-bestv[t]));
        int pos = atomicAdd(&g_ecnt[p], 1);
        g_eb[p * B_ + pos]     = b;
        g_ebslot[p * B_ + pos] = b * 3 + t;
        g_bp[b * 3 + t] = p;
        g_bw[b * 3 + t] = wv;
    }
}

// ---------------- kernel 4a: sparse expert partial-h (chunk-parallel) ----------------
// grid (P_, NT, SCMAX), 256 threads. Block = (expert p, gene tile ti, chunk c).
// Chunk-parallel: routing skew no longer serializes hot experts.
__global__ __launch_bounds__(256) void k_expertA(const float* __restrict__ xr,
                                                 const float* __restrict__ xc,
                                                 const float* __restrict__ xm,
                                                 const float* __restrict__ W1) {
    const int p  = blockIdx.x;
    const int cnt = g_ecnt[p];
    const int cs = blockIdx.z * 8;
    if (cs >= cnt) return;
    const int ti = blockIdx.y;
    const int scn = min(8, cnt - cs);
    const int ng  = g_ng[p];
    const int ng3 = 3 * ng;
    const int r0 = (ng3 * ti) / NT;
    const int r1 = (ng3 * (ti + 1)) / NT;
    const int t = threadIdx.x;
    const int hg = t & 15;     // 4 h cols: hg*4
    const int rg = t >> 4;     // 16 row groups

    __shared__ int sgo[128];                       // (o<<16)|gene per row
    __shared__ __align__(16) float xs[128 * 8];    // [row][sample]
    __shared__ float red[8 * H_ * 17];             // [s][h][rg pad 17]
    __shared__ int sb_b[8], sb_bslot[8];

    if (t < 8) {
        int idx = cs + ((t < scn) ? t : 0);
        sb_b[t]     = g_eb[p * B_ + idx];
        sb_bslot[t] = g_ebslot[p * B_ + idx];
    }

    ull acc[4][4];
#pragma unroll
    for (int a = 0; a < 4; a++)
#pragma unroll
        for (int sp = 0; sp < 4; sp++) acc[a][sp] = 0ULL;

    for (int rb = r0; rb < r1; rb += 128) {
        const int nr = min(128, r1 - rb);
        __syncthreads();    // prev compute done reading xs/sgo; sb_b visible
        if (t < nr) {
            int r = rb + t;
            int o = r / ng;
            int gene = g_glist[p * G_ + (r - o * ng)];
            sgo[t] = (o << 16) | gene;
        }
        __syncthreads();
        // gather x[row][sample] (L2 resident)
        for (int i = t; i < nr * 8; i += 256) {
            int j = i >> 3, s = i & 7;
            int code = sgo[j];
            int o = code >> 16, gene = code & 0xFFFF;
            const float* xp = (o == 0) ? xr : ((o == 1) ? xc : xm);
            xs[i] = xp[(size_t)sb_b[s] * G_ + gene];
        }
        __syncthreads();
        // compute: batch-4 independent W1 LDG.128 per thread (MLP), then packed fma
        for (int j = rg; j < nr; j += 64) {
            float4 w[4];
#pragma unroll
            for (int u = 0; u < 4; u++) {
                int jj = j + u * 16;
                if (jj < nr) {
                    int code = sgo[jj];
                    w[u] = *(const float4*)(W1 + ((size_t)p * D_ + (code >> 16) * G_
                                                  + (code & 0xFFFF)) * H_ + hg * 4);
                }
            }
#pragma unroll
            for (int u = 0; u < 4; u++) {
                int jj = j + u * 16;
                if (jj < nr) {
                    ull wb0, wb1, wb2, wb3;
                    asm("mov.b64 %0, {%1,%1};" : "=l"(wb0) : "r"(__float_as_uint(w[u].x)));
                    asm("mov.b64 %0, {%1,%1};" : "=l"(wb1) : "r"(__float_as_uint(w[u].y)));
                    asm("mov.b64 %0, {%1,%1};" : "=l"(wb2) : "r"(__float_as_uint(w[u].z)));
                    asm("mov.b64 %0, {%1,%1};" : "=l"(wb3) : "r"(__float_as_uint(w[u].w)));
                    const ull* xv = (const ull*)&xs[jj * 8];
#pragma unroll
                    for (int sp = 0; sp < 4; sp++) {
                        ull x2 = xv[sp];
                        asm("fma.rn.f32x2 %0, %1, %2, %0;" : "+l"(acc[0][sp]) : "l"(x2), "l"(wb0));
                        asm("fma.rn.f32x2 %0, %1, %2, %0;" : "+l"(acc[1][sp]) : "l"(x2), "l"(wb1));
                        asm("fma.rn.f32x2 %0, %1, %2, %0;" : "+l"(acc[2][sp]) : "l"(x2), "l"(wb2));
                        asm("fma.rn.f32x2 %0, %1, %2, %0;" : "+l"(acc[3][sp]) : "l"(x2), "l"(wb3));
                    }
                }
            }
        }
    }
    // unpack accs into red[s][h][rg]
    __syncthreads();
#pragma unroll
    for (int hc = 0; hc < 4; hc++)
#pragma unroll
        for (int sp = 0; sp < 4; sp++) {
            unsigned lo, hi;
            asm("mov.b64 {%0,%1}, %2;" : "=r"(lo), "=r"(hi) : "l"(acc[hc][sp]));
            int h = hg * 4 + hc;
            red[((2 * sp) * H_ + h) * 17 + rg]     = __uint_as_float(lo);
            red[((2 * sp + 1) * H_ + h) * 17 + rg] = __uint_as_float(hi);
        }
    __syncthreads();
    // reduce 16 row-groups, write partials
#pragma unroll
    for (int rep = 0; rep < 2; rep++) {
        int v = t + rep * 256;
        int h = v & 63, s = v >> 6;
        float sum = 0.f;
#pragma unroll
        for (int g16 = 0; g16 < 16; g16++)
            sum += red[(s * H_ + h) * 17 + g16];
        if (s < scn)
            g_hpart[(size_t)sb_bslot[s] * (NT * H_) + ti * H_ + h] = sum;
    }
}

// ---------------- kernel 4b: tile-sum + BN + ReLU + W2 + gate + classifier ----------------
// grid B_, 192 threads (3 slots x 64 h).
__global__ __launch_bounds__(192) void k_post(const float* __restrict__ b1,
                                              const float* __restrict__ bn_g,
                                              const float* __restrict__ bn_b,
                                              const float* __restrict__ bn_m,
                                              const float* __restrict__ bn_v,
                                              const float* __restrict__ W2,
                                              const float* __restrict__ b2,
                                              const float* __restrict__ cw1,
                                              const float* __restrict__ cb1,
                                              const float* __restrict__ cw2,
                                              const float* __restrict__ cb2,
                                              float* __restrict__ d_out) {
    const int b = blockIdx.x;
    const int t = threadIdx.x;
    const int slot = t >> 6, h = t & 63;
    __shared__ float hfm[3][H_];
    __shared__ float sfeat[3 * O_];
    __shared__ float feat[O_];
    __shared__ float hid[CH_];

    {
        int bslot = b * 3 + slot;
        int p = g_bp[bslot];
        float v = 0.f;
#pragma unroll
        for (int ti = 0; ti < NT; ti++)
            v += g_hpart[(size_t)bslot * (NT * H_) + ti * H_ + h];
        float sc  = bn_g[p * H_ + h] * rsqrtf(bn_v[p * H_ + h] + EPS_);
        float off = (b1[p * H_ + h] - bn_m[p * H_ + h]) * sc + bn_b[p * H_ + h];
        hfm[slot][h] = fmaxf(fmaf(v, sc, off), 0.f);
    }
    __syncthreads();
    if (t < 3 * O_) {
        int sl = t >> 4, o = t & 15;
        int bslot = b * 3 + sl;
        int p = g_bp[bslot];
        float a = b2[p * O_ + o];
#pragma unroll 8
        for (int hh = 0; hh < H_; hh++)
            a = fmaf(hfm[sl][hh], W2[(p * H_ + hh) * O_ + o], a);
        sfeat[t] = g_bw[bslot] * a;
    }
    __syncthreads();
    if (t < O_)
        feat[t] = sfeat[t] + sfeat[O_ + t] + sfeat[2 * O_ + t];
    __syncthreads();
    if (t < CH_) {
        float v = cb1[t];
#pragma unroll
        for (int o = 0; o < O_; o++) v = fmaf(feat[o], cw1[o * CH_ + t], v);
        hid[t] = fmaxf(v, 0.f);
    }
    __syncthreads();
    if (t < C_) {
        float v = cb2[t];
#pragma unroll
        for (int ch = 0; ch < CH_; ch++) v = fmaf(hid[ch], cw2[ch * C_ + t], v);
        d_out[b * C_ + t] = v;
    }
}

// ---------------- launch ----------------
extern "C" void kernel_launch(void* const* d_in, const int* in_sizes, int n_in,
                              void* d_out, int out_size) {
    const float* x_rna    = (const float*)d_in[0];
    const float* x_cnv    = (const float*)d_in[1];
    const float* x_met    = (const float*)d_in[2];
    const float* gene_mask= (const float*)d_in[3];
    const float* gate_w1  = (const float*)d_in[4];
    const float* gate_b1  = (const float*)d_in[5];
    const float* gate_w2  = (const float*)d_in[6];
    const float* gate_b2  = (const float*)d_in[7];
    const float* W1       = (const float*)d_in[8];
    const float* b1       = (const float*)d_in[9];
    const float* bn_gamma = (const float*)d_in[10];
    const float* bn_beta  = (const float*)d_in[11];
    const float* bn_mean  = (const float*)d_in[12];
    const float* bn_var   = (const float*)d_in[13];
    const float* W2       = (const float*)d_in[14];
    const float* b2       = (const float*)d_in[15];
    const float* cls_w1   = (const float*)d_in[16];
    const float* cls_b1   = (const float*)d_in[17];
    const float* cls_w2   = (const float*)d_in[18];
    const float* cls_b2   = (const float*)d_in[19];
    float* out = (float*)d_out;

    k_gate1  <<<dim3(KSPLIT, 8), 256>>>(x_rna, gate_w1);
    k_mask   <<<P_, 128>>>(gene_mask);
    k_gate2  <<<B_, 128>>>(gate_b1, gate_w2, gate_b2, out);
    k_expertA<<<dim3(P_, NT, SCMAX), 256>>>(x_rna, x_cnv, x_met, W1);
    k_post   <<<B_, 192>>>(b1, bn_gamma, bn_beta, bn_mean, bn_var, W2, b2,
                           cls_w1, cls_b1, cls_w2, cls_b2, out);
}

// round 17
// speedup vs baseline: 1.8319x; 1.3679x over previous
#include <cuda_runtime.h>
#include <math.h>

#define B_  256
#define G_  4000
#define P_  128
#define H_  64
#define O_  16
#define GH_ 128
#define CH_ 8
#define C_  5
#define D_  12000
#define KSPLIT 16
#define KC 250        // G_/KSPLIT
#define NT  16        // gene tiles per expert in phase A
#define WMAX 224      // max compact work items (provably <= 208)
#define EPS_ 1e-5f

typedef unsigned long long ull;

// ---------------- scratch (__device__ globals; no allocs) ----------------
__device__ float g_part[KSPLIT * B_ * GH_];    // gate hidden partials [ks][b][h]
__device__ int   g_glist3[P_ * D_];            // expanded (o<<16)|gene rows per pathway
__device__ int   g_ng[P_];                     // active gene count per pathway
__device__ int   g_ecnt[P_];                   // samples routed to each expert
__device__ int   g_eb[P_ * B_];                // sample index per routed entry
__device__ int   g_ebslot[P_ * B_];            // b*3+slot per routed entry
__device__ int   g_bp[B_ * 3];                 // expert id per (b,slot)
__device__ float g_bw[B_ * 3];                 // gate weight per (b,slot)
__device__ float g_hpart[B_ * 3 * NT * H_];    // partial h sums [bslot][tile][h]
__device__ int   g_work[WMAX];                 // compact (p<<16)|chunk work list
__device__ int   g_nwork;                      // number of work items

// ---------------- kernel 1: gate hidden GEMM (k-split, f32x2 packed) ----------------
__global__ __launch_bounds__(256) void k_gate1(const float* __restrict__ x_rna,
                                               const float* __restrict__ gw1) {
    const int ks = blockIdx.x;
    const int sb = blockIdx.y;
    const int t  = threadIdx.x;
    const int k0 = ks * KC;
    __shared__ float xs[KC * 34];   // [k][s] padded to 34 (bank + 8B align)

    {   // stage x: warp w covers samples {w, w+8, w+16, w+24}; lanes over k
        const int w = t >> 5, lane = t & 31;
#pragma unroll
        for (int si = 0; si < 4; si++) {
            int s = w + si * 8;
            const float* xp = x_rna + (size_t)(sb * 32 + s) * G_ + k0;
            for (int k = lane; k < KC; k += 32)
                xs[k * 34 + s] = xp[k];
        }
    }
    __syncthreads();

    const int hq = t & 31;     // 4 h cols: hq*4
    const int sg = t >> 5;     // 8 groups x 4 samples
    const int s0 = sg * 4;

    ull acc[4][2];
#pragma unroll
    for (int i = 0; i < 4; i++) { acc[i][0] = 0ULL; acc[i][1] = 0ULL; }

    const float* wp = gw1 + (size_t)k0 * GH_ + hq * 4;
#pragma unroll 2
    for (int k = 0; k < KC; k++) {
        float4 w = *(const float4*)(wp + (size_t)k * GH_);
        ull x01 = *(const ull*)&xs[k * 34 + s0];
        ull x23 = *(const ull*)&xs[k * 34 + s0 + 2];
        ull wb0, wb1, wb2, wb3;
        asm("mov.b64 %0, {%1,%1};" : "=l"(wb0) : "r"(__float_as_uint(w.x)));
        asm("mov.b64 %0, {%1,%1};" : "=l"(wb1) : "r"(__float_as_uint(w.y)));
        asm("mov.b64 %0, {%1,%1};" : "=l"(wb2) : "r"(__float_as_uint(w.z)));
        asm("mov.b64 %0, {%1,%1};" : "=l"(wb3) : "r"(__float_as_uint(w.w)));
        asm("fma.rn.f32x2 %0, %1, %2, %0;" : "+l"(acc[0][0]) : "l"(x01), "l"(wb0));
        asm("fma.rn.f32x2 %0, %1, %2, %0;" : "+l"(acc[1][0]) : "l"(x01), "l"(wb1));
        asm("fma.rn.f32x2 %0, %1, %2, %0;" : "+l"(acc[2][0]) : "l"(x01), "l"(wb2));
        asm("fma.rn.f32x2 %0, %1, %2, %0;" : "+l"(acc[3][0]) : "l"(x01), "l"(wb3));
        asm("fma.rn.f32x2 %0, %1, %2, %0;" : "+l"(acc[0][1]) : "l"(x23), "l"(wb0));
        asm("fma.rn.f32x2 %0, %1, %2, %0;" : "+l"(acc[1][1]) : "l"(x23), "l"(wb1));
        asm("fma.rn.f32x2 %0, %1, %2, %0;" : "+l"(acc[2][1]) : "l"(x23), "l"(wb2));
        asm("fma.rn.f32x2 %0, %1, %2, %0;" : "+l"(acc[3][1]) : "l"(x23), "l"(wb3));
    }

    float v[4][2][2];   // [hc][sp][lo/hi]
#pragma unroll
    for (int hc = 0; hc < 4; hc++)
#pragma unroll
        for (int sp = 0; sp < 2; sp++) {
            unsigned lo, hi;
            asm("mov.b64 {%0,%1}, %2;" : "=r"(lo), "=r"(hi) : "l"(acc[hc][sp]));
            v[hc][sp][0] = __uint_as_float(lo);
            v[hc][sp][1] = __uint_as_float(hi);
        }
#pragma unroll
    for (int sp = 0; sp < 2; sp++)
#pragma unroll
        for (int sg2 = 0; sg2 < 2; sg2++) {
            int s = s0 + 2 * sp + sg2;
            float4 o4 = make_float4(v[0][sp][sg2], v[1][sp][sg2], v[2][sp][sg2], v[3][sp][sg2]);
            *(float4*)&g_part[(size_t)(ks * B_ + sb * 32 + s) * GH_ + hq * 4] = o4;
        }
}

// ---------------- kernel 2: mask compaction -> expanded (o,gene) list ----------------
// grid P_, 128 threads. Warp q handles genes [q*1024, ...).
__global__ __launch_bounds__(128) void k_mask(const float* __restrict__ mask) {
    const int p = blockIdx.x;
    const int t = threadIdx.x;
    const int q = t >> 5, lane = t & 31;
    __shared__ int qlist[4][1024];
    __shared__ int qcnt[4];
    __shared__ int qoff[4];
    __shared__ int sng;

    const int gstart = q * 1024;
    const int gend   = min(G_, gstart + 1024);
    const int niter  = (gend - gstart) >> 5;   // 32,32,32,29
    int base = 0;
    const unsigned lm = (1u << lane) - 1u;

    for (int it = 0; it < niter; it += 4) {
        float m[4];
#pragma unroll
        for (int u = 0; u < 4; u++) {
            int iu = it + u;
            m[u] = (iu < niter) ? mask[(size_t)(gstart + iu * 32 + lane) * P_ + p] : 0.0f;
        }
#pragma unroll
        for (int u = 0; u < 4; u++) {
            int iu = it + u;
            if (iu < niter) {
                unsigned bal = __ballot_sync(0xffffffffu, m[u] != 0.0f);
                if (m[u] != 0.0f)
                    qlist[q][base + __popc(bal & lm)] = gstart + iu * 32 + lane;
                base += __popc(bal);
            }
        }
    }
    if (lane == 0) qcnt[q] = base;
    __syncthreads();
    if (t == 0) {
        int s = 0;
#pragma unroll
        for (int i = 0; i < 4; i++) { qoff[i] = s; s += qcnt[i]; }
        sng = s;
        g_ng[p] = s;
        g_ecnt[p] = 0;
    }
    __syncthreads();
    const int ng = sng;
    for (int i = lane; i < qcnt[q]; i += 32) {
        int g = qlist[q][i];
        int idx = qoff[q] + i;
        g_glist3[p * D_ + idx]          = g;
        g_glist3[p * D_ + ng + idx]     = (1 << 16) | g;
        g_glist3[p * D_ + 2 * ng + idx] = (2 << 16) | g;
    }
}

// ---------------- kernel 3: reduce + logits + top3 + routing ----------------
__global__ __launch_bounds__(128) void k_gate2(const float* __restrict__ gb1,
                                               const float* __restrict__ gw2,
                                               const float* __restrict__ gb2,
                                               float* __restrict__ d_out) {
    const int b = blockIdx.x;
    const int t = threadIdx.x;
    __shared__ float sh[GH_];
    __shared__ float av[P_], cv[P_];
    __shared__ int   ci[P_];
    __shared__ float bestv[3];
    __shared__ int   besti[3];

    float s = 0.f;
#pragma unroll
    for (int ks = 0; ks < KSPLIT; ks++)
        s += g_part[(size_t)(ks * B_ + b) * GH_ + t];
    s += gb1[t];
    sh[t] = fmaxf(s, 0.f);
    __syncthreads();

    float lg = gb2[t];
#pragma unroll 4
    for (int h = 0; h < GH_; h++)
        lg = fmaf(sh[h], gw2[h * P_ + t], lg);
    av[t] = lg;
    __syncthreads();

    for (int r = 0; r < 3; r++) {
        cv[t] = av[t]; ci[t] = t;
        __syncthreads();
        for (int w = 64; w > 0; w >>= 1) {
            if (t < w) {
                float v2 = cv[t + w]; int i2 = ci[t + w];
                if (v2 > cv[t] || (v2 == cv[t] && i2 < ci[t])) { cv[t] = v2; ci[t] = i2; }
            }
            __syncthreads();
        }
        if (t == 0) { bestv[r] = cv[0]; besti[r] = ci[0]; }
        __syncthreads();
        if (t == besti[r]) av[t] = -INFINITY;
        __syncthreads();
    }

    float gw = 0.f;
#pragma unroll
    for (int r = 0; r < 3; r++)
        if (t == besti[r]) gw = 1.f / (1.f + expf(-bestv[r]));
    d_out[B_ * C_ + b * P_ + t] = gw;   // gate_weights after logits

    if (t < 3) {
        int p = besti[t];
        float wv = 1.f / (1.f + expf(-bestv[t]));
        int pos = atomicAdd(&g_ecnt[p], 1);
        g_eb[p * B_ + pos]     = b;
        g_ebslot[p * B_ + pos] = b * 3 + t;
        g_bp[b * 3 + t] = p;
        g_bw[b * 3 + t] = wv;
    }
}

// ---------------- kernel 3b: compact work list ----------------
// 1 block, 128 threads. Items ordered by (p, chunk) -> deterministic.
__global__ __launch_bounds__(128) void k_worklist() {
    __shared__ int nch[P_], off[P_];
    const int t = threadIdx.x;
    int n = (g_ecnt[t] + 7) >> 3;
    nch[t] = n;
    __syncthreads();
    if (t == 0) {
        int s = 0;
        for (int i = 0; i < P_; i++) { off[i] = s; s += nch[i]; }
        g_nwork = s;
    }
    __syncthreads();
    for (int c = 0; c < nch[t]; c++)
        g_work[off[t] + c] = (t << 16) | c;
}

// ---------------- kernel 4a: sparse expert partial-h (work-list driven) ----------------
// grid (WMAX, NT), 256 threads, 4 CTAs/SM target. Block = (work item, gene tile).
__global__ __launch_bounds__(256, 4) void k_expertA(const float* __restrict__ xr,
                                                    const float* __restrict__ xc,
                                                    const float* __restrict__ xm,
                                                    const float* __restrict__ W1) {
    const int wi = blockIdx.x;
    if (wi >= g_nwork) return;
    const int wcode = g_work[wi];
    const int p  = wcode >> 16;
    const int cs = (wcode & 0xFFFF) * 8;
    const int cnt = g_ecnt[p];
    const int ti = blockIdx.y;
    const int scn = min(8, cnt - cs);
    const int ng  = g_ng[p];
    const int ng3 = 3 * ng;
    const int r0 = (ng3 * ti) / NT;
    const int r1 = (ng3 * (ti + 1)) / NT;
    const int t = threadIdx.x;
    const int hg = t & 15;     // 4 h cols: hg*4
    const int rg = t >> 4;     // 16 row groups

    __shared__ int sgo[128];                       // (o<<16)|gene per row
    __shared__ __align__(16) float xs[128 * 8];    // [row][sample]
    __shared__ float red[8 * H_ * 9];              // [s][h][warp pad 9] (post-shfl)
    __shared__ int sb_b[8], sb_bslot[8];

    if (t < 8) {
        int idx = cs + ((t < scn) ? t : 0);
        sb_b[t]     = g_eb[p * B_ + idx];
        sb_bslot[t] = g_ebslot[p * B_ + idx];
    }

    ull acc[4][4];
#pragma unroll
    for (int a = 0; a < 4; a++)
#pragma unroll
        for (int sp = 0; sp < 4; sp++) acc[a][sp] = 0ULL;

    for (int rb = r0; rb < r1; rb += 128) {
        const int nr = min(128, r1 - rb);
        __syncthreads();    // prev compute done reading xs/sgo; sb_b visible
        if (t < nr)
            sgo[t] = g_glist3[p * D_ + rb + t];
        __syncthreads();
        // gather x[row][sample] (L2 resident)
        for (int i = t; i < nr * 8; i += 256) {
            int j = i >> 3, s = i & 7;
            int code = sgo[j];
            int o = code >> 16, gene = code & 0xFFFF;
            const float* xp = (o == 0) ? xr : ((o == 1) ? xc : xm);
            xs[i] = xp[(size_t)sb_b[s] * G_ + gene];
        }
        __syncthreads();
        // compute: batch-4 independent W1 LDG.128 per thread (MLP), then packed fma
        for (int j = rg; j < nr; j += 64) {
            float4 w[4];
#pragma unroll
            for (int u = 0; u < 4; u++) {
                int jj = j + u * 16;
                if (jj < nr) {
                    int code = sgo[jj];
                    w[u] = *(const float4*)(W1 + ((size_t)p * D_ + (code >> 16) * G_
                                                  + (code & 0xFFFF)) * H_ + hg * 4);
                }
            }
#pragma unroll
            for (int u = 0; u < 4; u++) {
                int jj = j + u * 16;
                if (jj < nr) {
                    ull wb0, wb1, wb2, wb3;
                    asm("mov.b64 %0, {%1,%1};" : "=l"(wb0) : "r"(__float_as_uint(w[u].x)));
                    asm("mov.b64 %0, {%1,%1};" : "=l"(wb1) : "r"(__float_as_uint(w[u].y)));
                    asm("mov.b64 %0, {%1,%1};" : "=l"(wb2) : "r"(__float_as_uint(w[u].z)));
                    asm("mov.b64 %0, {%1,%1};" : "=l"(wb3) : "r"(__float_as_uint(w[u].w)));
                    const ull* xv = (const ull*)&xs[jj * 8];
#pragma unroll
                    for (int sp = 0; sp < 4; sp++) {
                        ull x2 = xv[sp];
                        asm("fma.rn.f32x2 %0, %1, %2, %0;" : "+l"(acc[0][sp]) : "l"(x2), "l"(wb0));
                        asm("fma.rn.f32x2 %0, %1, %2, %0;" : "+l"(acc[1][sp]) : "l"(x2), "l"(wb1));
                        asm("fma.rn.f32x2 %0, %1, %2, %0;" : "+l"(acc[2][sp]) : "l"(x2), "l"(wb2));
                        asm("fma.rn.f32x2 %0, %1, %2, %0;" : "+l"(acc[3][sp]) : "l"(x2), "l"(wb3));
                    }
                }
            }
        }
    }
    // intra-warp pre-reduce: lanes l and l^16 share hg, hold rg pair (2w, 2w+1)
    __syncthreads();
    const int wlane = t & 31;
    const int warp  = t >> 5;   // 8 warps -> 8 columns
#pragma unroll
    for (int hc = 0; hc < 4; hc++)
#pragma unroll
        for (int sp = 0; sp < 4; sp++) {
            unsigned lo, hi;
            asm("mov.b64 {%0,%1}, %2;" : "=r"(lo), "=r"(hi) : "l"(acc[hc][sp]));
            float flo = __uint_as_float(lo);
            float fhi = __uint_as_float(hi);
            flo += __shfl_xor_sync(0xffffffffu, flo, 16);
            fhi += __shfl_xor_sync(0xffffffffu, fhi, 16);
            if (wlane < 16) {
                int h = hg * 4 + hc;
                red[((2 * sp) * H_ + h) * 9 + warp]     = flo;
                red[((2 * sp + 1) * H_ + h) * 9 + warp] = fhi;
            }
        }
    __syncthreads();
    // reduce 8 warp-columns, write partials
#pragma unroll
    for (int rep = 0; rep < 2; rep++) {
        int v = t + rep * 256;
        int h = v & 63, s = v >> 6;
        float sum = 0.f;
#pragma unroll
        for (int g8 = 0; g8 < 8; g8++)
            sum += red[(s * H_ + h) * 9 + g8];
        if (s < scn)
            g_hpart[(size_t)sb_bslot[s] * (NT * H_) + ti * H_ + h] = sum;
    }
}

// ---------------- kernel 4b: tile-sum + BN + ReLU + W2 + gate + classifier ----------------
__global__ __launch_bounds__(192) void k_post(const float* __restrict__ b1,
                                              const float* __restrict__ bn_g,
                                              const float* __restrict__ bn_b,
                                              const float* __restrict__ bn_m,
                                              const float* __restrict__ bn_v,
                                              const float* __restrict__ W2,
                                              const float* __restrict__ b2,
                                              const float* __restrict__ cw1,
                                              const float* __restrict__ cb1,
                                              const float* __restrict__ cw2,
                                              const float* __restrict__ cb2,
                                              float* __restrict__ d_out) {
    const int b = blockIdx.x;
    const int t = threadIdx.x;
    const int slot = t >> 6, h = t & 63;
    __shared__ float hfm[3][H_];
    __shared__ float sfeat[3 * O_];
    __shared__ float feat[O_];
    __shared__ float hid[CH_];

    {
        int bslot = b * 3 + slot;
        int p = g_bp[bslot];
        float v = 0.f;
#pragma unroll
        for (int ti = 0; ti < NT; ti++)
            v += g_hpart[(size_t)bslot * (NT * H_) + ti * H_ + h];
        float sc  = bn_g[p * H_ + h] * rsqrtf(bn_v[p * H_ + h] + EPS_);
        float off = (b1[p * H_ + h] - bn_m[p * H_ + h]) * sc + bn_b[p * H_ + h];
        hfm[slot][h] = fmaxf(fmaf(v, sc, off), 0.f);
    }
    __syncthreads();
    if (t < 3 * O_) {
        int sl = t >> 4, o = t & 15;
        int bslot = b * 3 + sl;
        int p = g_bp[bslot];
        float a = b2[p * O_ + o];
#pragma unroll 8
        for (int hh = 0; hh < H_; hh++)
            a = fmaf(hfm[sl][hh], W2[(p * H_ + hh) * O_ + o], a);
        sfeat[t] = g_bw[bslot] * a;
    }
    __syncthreads();
    if (t < O_)
        feat[t] = sfeat[t] + sfeat[O_ + t] + sfeat[2 * O_ + t];
    __syncthreads();
    if (t < CH_) {
        float v = cb1[t];
#pragma unroll
        for (int o = 0; o < O_; o++) v = fmaf(feat[o], cw1[o * CH_ + t], v);
        hid[t] = fmaxf(v, 0.f);
    }
    __syncthreads();
    if (t < C_) {
        float v = cb2[t];
#pragma unroll
        for (int ch = 0; ch < CH_; ch++) v = fmaf(hid[ch], cw2[ch * C_ + t], v);
        d_out[b * C_ + t] = v;
    }
}

// ---------------- launch ----------------
extern "C" void kernel_launch(void* const* d_in, const int* in_sizes, int n_in,
                              void* d_out, int out_size) {
    const float* x_rna    = (const float*)d_in[0];
    const float* x_cnv    = (const float*)d_in[1];
    const float* x_met    = (const float*)d_in[2];
    const float* gene_mask= (const float*)d_in[3];
    const float* gate_w1  = (const float*)d_in[4];
    const float* gate_b1  = (const float*)d_in[5];
    const float* gate_w2  = (const float*)d_in[6];
    const float* gate_b2  = (const float*)d_in[7];
    const float* W1       = (const float*)d_in[8];
    const float* b1       = (const float*)d_in[9];
    const float* bn_gamma = (const float*)d_in[10];
    const float* bn_beta  = (const float*)d_in[11];
    const float* bn_mean  = (const float*)d_in[12];
    const float* bn_var   = (const float*)d_in[13];
    const float* W2       = (const float*)d_in[14];
    const float* b2       = (const float*)d_in[15];
    const float* cls_w1   = (const float*)d_in[16];
    const float* cls_b1   = (const float*)d_in[17];
    const float* cls_w2   = (const float*)d_in[18];
    const float* cls_b2   = (const float*)d_in[19];
    float* out = (float*)d_out;

    k_gate1   <<<dim3(KSPLIT, 8), 256>>>(x_rna, gate_w1);
    k_mask    <<<P_, 128>>>(gene_mask);
    k_gate2   <<<B_, 128>>>(gate_b1, gate_w2, gate_b2, out);
    k_worklist<<<1, 128>>>();
    k_expertA <<<dim3(WMAX, NT), 256>>>(x_rna, x_cnv, x_met, W1);
    k_post    <<<B_, 192>>>(b1, bn_gamma, bn_beta, bn_mean, bn_var, W2, b2,
                            cls_w1, cls_b1, cls_w2, cls_b2, out);
}